// round 15
// baseline (speedup 1.0000x reference)
#include <cuda_runtime.h>
#include <math.h>

#define BN   20800
#define T_   24
#define F_   64
#define H_   128
#define TRR  48
#define NCTA 434          // ceil(20800/48)
#define NTH  512          // 16 warps, 8 output cols per warp

typedef unsigned int uint32;

// ---------------- global scratch ----------------
// prepacked B-fragments (tf32 hi term only), float2 per (tile, lane)  [m16n8k8]
__device__ float2 g_wihP[384  * 32];   // w_ih  [384x64]  : 48 nt x 8 kt
__device__ float2 g_whhP[768  * 32];   // w_hh  [384x128] : 48 nt x 16 kt
__device__ float2 g_gwP [1024 * 32];   // gate_w[256x256] : 32 nt x 32 kt
__device__ float2 g_owP [512  * 32];   // out_w [128x256] : 16 nt x 32 kt

// ---------------- helpers ----------------
__device__ __forceinline__ void tf32_split(float v, float& hi, float& lo) {
    uint32 b;
    asm("cvt.rna.tf32.f32 %0, %1;" : "=r"(b) : "f"(v));
    hi = __uint_as_float(b);
    float r = v - hi;
    asm("cvt.rna.tf32.f32 %0, %1;" : "=r"(b) : "f"(r));
    lo = __uint_as_float(b);
}

__device__ __forceinline__ float tf32_rna(float v) {
    uint32 b;
    asm("cvt.rna.tf32.f32 %0, %1;" : "=r"(b) : "f"(v));
    return __uint_as_float(b);
}

__device__ __forceinline__ float sigmoidf_(float v) {
    return __fdividef(1.0f, 1.0f + __expf(-v));
}
__device__ __forceinline__ float tanhf_(float v) {
    return __fdividef(2.0f, 1.0f + __expf(-2.0f * v)) - 1.0f;
}

// D += A * B, m16n8k8 tf32 (row.col). a: 4 b32 regs, b: 2 b32 regs.
__device__ __forceinline__ void mma8(float d[4], const uint32* a, float2 b) {
    asm volatile(
        "mma.sync.aligned.m16n8k8.row.col.f32.tf32.tf32.f32 "
        "{%0,%1,%2,%3},{%4,%5,%6,%7},{%8,%9},{%0,%1,%2,%3};"
        : "+f"(d[0]), "+f"(d[1]), "+f"(d[2]), "+f"(d[3])
        : "r"(a[0]), "r"(a[1]), "r"(a[2]), "r"(a[3]),
          "r"(__float_as_uint(b.x)), "r"(__float_as_uint(b.y)));
}

// A-fragment smem layout: [term(2)][mt(3)][kt(KT)][lane(32)][reg(4)] floats
// term 0 (hi) feeds MMA; term 1 (lo) only completes full-precision state reads.
__device__ __forceinline__ void frag_write(float* base, int KT, int term,
                                           int mt, int kt, int m, int k, float v) {
    int lp = ((m & 7) << 2) | (k & 3);
    int rp = ((m >> 3) & 1) | (((k >> 2) & 1) << 1);
    base[(((term * 3 + mt) * KT + kt) * 32 + lp) * 4 + rp] = v;
}

// read back element (m,k) as hi + lo
__device__ __forceinline__ float frag_read2(const float* base, int KT,
                                            int mt, int kt, int m, int k) {
    int lp = ((m & 7) << 2) | (k & 3);
    int rp = ((m >> 3) & 1) | (((k >> 2) & 1) << 1);
    return base[(((0 * 3 + mt) * KT + kt) * 32 + lp) * 4 + rp]
         + base[(((1 * 3 + mt) * KT + kt) * 32 + lp) * 4 + rp];
}

// ---------------- weight prepack into B-fragment order (hi term only) ------
__global__ void prepack(const float* __restrict__ w_ih, const float* __restrict__ w_hh,
                        const float* __restrict__ gw,  const float* __restrict__ ow)
{
    int idx = blockIdx.x * blockDim.x + threadIdx.x;   // 2688 tiles * 32 lanes
    if (idx >= 2688 * 32) return;
    int lane = idx & 31, tile = idx >> 5;
    int g = lane >> 2, tig = lane & 3;
    const float* W; float2* dst; int ld, lt;
    if      (tile < 384)  { W = w_ih; dst = g_wihP; ld = 64;  lt = tile; }
    else if (tile < 1152) { W = w_hh; dst = g_whhP; ld = 128; lt = tile - 384; }
    else if (tile < 2176) { W = gw;   dst = g_gwP;  ld = 256; lt = tile - 1152; }
    else                  { W = ow;   dst = g_owP;  ld = 256; lt = tile - 2176; }
    int KT = ld >> 3;
    int n = (lt / KT) * 8 + g;            // output row
    int k = (lt % KT) * 8 + tig;          // input col
    dst[lt * 32 + lane] = make_float2(tf32_rna(W[n * ld + k]),
                                      tf32_rna(W[n * ld + k + 4]));
}

// ---------------- Fused 2-layer GRU over T steps ----------------
// 16 warps; warp w owns output columns [8w, 8w+8) (one n8 block).
// 1-term tf32 MMAs (AH*BH); state h0/h1 kept hi+lo in smem for exact carry.
__global__ __launch_bounds__(NTH, 1)
void gru_fused(const float* __restrict__ x,
               const float* __restrict__ b_ih, const float* __restrict__ b_hh,
               const float* __restrict__ gate_b, const float* __restrict__ out_b,
               float* __restrict__ out)
{
    extern __shared__ float sm[];
    float* xf  = sm;            // [2][3][8][32][4]  = 6144  (x tile; hi term used)
    float* h0f = sm + 6144;     // [2][3][16][32][4] = 12288 (layer0 h, hi+lo)
    float* h1f = sm + 18432;    // 12288 (layer1 h, hi+lo)
    float* rhf = sm + 30720;    // 12288 (r * h1; hi term used)
    const int tid = threadIdx.x;
    const int w = tid >> 5, lane = tid & 31;
    const int g = lane >> 2, tig = lane & 3;
    const int bn0 = blockIdx.x * TRR;

    // zero h0f + h1f (contiguous 24576 floats)
    for (int i = tid; i < 24576; i += NTH) h0f[i] = 0.f;

    const int c0 = 8 * w + 2 * tig;
    // layer0 biases
    float br0 = b_ih[c0]       + b_hh[c0],       br1 = b_ih[c0+1]     + b_hh[c0+1];
    float bz0 = b_ih[128 + c0] + b_hh[128 + c0], bz1 = b_ih[129 + c0] + b_hh[129 + c0];
    float bx0 = b_ih[256 + c0], bx1 = b_ih[257 + c0];
    float bh0 = b_hh[256 + c0], bh1 = b_hh[257 + c0];
    // layer1 biases
    float bgr0 = gate_b[c0],       bgr1 = gate_b[c0 + 1];
    float bgz0 = gate_b[128 + c0], bgz1 = gate_b[129 + c0];
    float bo0  = out_b[c0],        bo1  = out_b[c0 + 1];

    // stage x(0): hi term only (lo never read)
    #pragma unroll
    for (int i = 0; i < 6; ++i) {
        int idx = tid + i * NTH;            // 0..3071
        int row = idx >> 6, col = idx & 63;
        int bn = bn0 + row;
        float v = (bn < BN) ? x[(size_t)bn * T_ * F_ + col] : 0.f;
        frag_write(xf, 8, 0, row >> 4, col >> 3, row, col, tf32_rna(v));
    }
    __syncthreads();   // init + x(0) visible

    for (int t = 0; t < T_; ++t) {
        // ==== layer0 GEMMs (1-term) ====
        float aR[3][4], aZ[3][4], aNX[3][4], aNH[3][4];
        #pragma unroll
        for (int mt = 0; mt < 3; ++mt) {
            aR[mt][0] = br0; aR[mt][1] = br1; aR[mt][2] = br0; aR[mt][3] = br1;
            aZ[mt][0] = bz0; aZ[mt][1] = bz1; aZ[mt][2] = bz0; aZ[mt][3] = bz1;
            aNX[mt][0] = bx0; aNX[mt][1] = bx1; aNX[mt][2] = bx0; aNX[mt][3] = bx1;
            aNH[mt][0] = bh0; aNH[mt][1] = bh1; aNH[mt][2] = bh0; aNH[mt][3] = bh1;
        }
        #pragma unroll
        for (int kt = 0; kt < 8; ++kt) {        // x-part, K=64
            uint4 ah[3];
            #pragma unroll
            for (int mt = 0; mt < 3; ++mt)
                ah[mt] = ((const uint4*)xf)[((0 * 3 + mt) * 8 + kt) * 32 + lane];
            float2 bR = g_wihP[((     w) * 8 + kt) * 32 + lane];
            float2 bZ = g_wihP[((16 + w) * 8 + kt) * 32 + lane];
            float2 bN = g_wihP[((32 + w) * 8 + kt) * 32 + lane];
            #pragma unroll
            for (int mt = 0; mt < 3; ++mt) {
                const uint32* AH = (const uint32*)&ah[mt];
                mma8(aR[mt],  AH, bR);
                mma8(aZ[mt],  AH, bZ);
                mma8(aNX[mt], AH, bN);
            }
        }
        #pragma unroll
        for (int kt = 0; kt < 16; ++kt) {       // h-part, K=128 (n gate into aNH)
            uint4 ah[3];
            #pragma unroll
            for (int mt = 0; mt < 3; ++mt)
                ah[mt] = ((const uint4*)h0f)[((0 * 3 + mt) * 16 + kt) * 32 + lane];
            float2 bR = g_whhP[((     w) * 16 + kt) * 32 + lane];
            float2 bZ = g_whhP[((16 + w) * 16 + kt) * 32 + lane];
            float2 bN = g_whhP[((32 + w) * 16 + kt) * 32 + lane];
            #pragma unroll
            for (int mt = 0; mt < 3; ++mt) {
                const uint32* AH = (const uint32*)&ah[mt];
                mma8(aR[mt],  AH, bR);
                mma8(aZ[mt],  AH, bZ);
                mma8(aNH[mt], AH, bN);
            }
        }
        __syncthreads();   // S2: all reads of h0f/xf done

        // ==== layer0 epilogue: h0(t) -> h0f (hi+lo; exact state carry) ====
        #pragma unroll
        for (int mt = 0; mt < 3; ++mt)
            #pragma unroll
            for (int r = 0; r < 4; ++r) {
                int m   = mt * 16 + g + 8 * (r >> 1);
                int col = c0 + (r & 1);
                float hold = frag_read2(h0f, 16, mt, col >> 3, m, col);
                float rr = sigmoidf_(aR[mt][r]);
                float zz = sigmoidf_(aZ[mt][r]);
                float n  = tanhf_(aNX[mt][r] + rr * aNH[mt][r]);
                float hn = (1.f - zz) * n + zz * hold;
                float hi, lo; tf32_split(hn, hi, lo);
                frag_write(h0f, 16, 0, mt, col >> 3, m, col, hi);
                frag_write(h0f, 16, 1, mt, col >> 3, m, col, lo);
            }
        __syncthreads();   // S3: h0f(t) ready for layer1

        // ==== stage x(t+1) into xf (overlaps with gates GEMM below) ====
        if (t + 1 < T_) {
            #pragma unroll
            for (int i = 0; i < 6; ++i) {
                int idx = tid + i * NTH;        // 0..3071
                int row = idx >> 6, col = idx & 63;
                int bn = bn0 + row;
                float v = (bn < BN) ? x[((size_t)bn * T_ + t + 1) * F_ + col] : 0.f;
                frag_write(xf, 8, 0, row >> 4, col >> 3, row, col, tf32_rna(v));
            }
        }

        // ==== layer1 gates GEMM (+ candidate x-half) ====
        float aR1[3][4], aZ1[3][4], aC[3][4];
        #pragma unroll
        for (int mt = 0; mt < 3; ++mt) {
            aR1[mt][0] = bgr0; aR1[mt][1] = bgr1; aR1[mt][2] = bgr0; aR1[mt][3] = bgr1;
            aZ1[mt][0] = bgz0; aZ1[mt][1] = bgz1; aZ1[mt][2] = bgz0; aZ1[mt][3] = bgz1;
            aC[mt][0]  = bo0;  aC[mt][1]  = bo1;  aC[mt][2]  = bo0;  aC[mt][3]  = bo1;
        }
        #pragma unroll
        for (int kt = 0; kt < 16; ++kt) {       // x half: A = h0f (hi)
            uint4 ah[3];
            #pragma unroll
            for (int mt = 0; mt < 3; ++mt)
                ah[mt] = ((const uint4*)h0f)[((0 * 3 + mt) * 16 + kt) * 32 + lane];
            float2 bR = g_gwP[((     w) * 32 + kt) * 32 + lane];
            float2 bZ = g_gwP[((16 + w) * 32 + kt) * 32 + lane];
            float2 bC = g_owP[(      w  * 32 + kt) * 32 + lane];
            #pragma unroll
            for (int mt = 0; mt < 3; ++mt) {
                const uint32* AH = (const uint32*)&ah[mt];
                mma8(aR1[mt], AH, bR);
                mma8(aZ1[mt], AH, bZ);
                mma8(aC[mt],  AH, bC);
            }
        }
        #pragma unroll
        for (int kt = 0; kt < 16; ++kt) {       // h half: A = h1f (hi), gates only
            uint4 ah[3];
            #pragma unroll
            for (int mt = 0; mt < 3; ++mt)
                ah[mt] = ((const uint4*)h1f)[((0 * 3 + mt) * 16 + kt) * 32 + lane];
            float2 bR = g_gwP[((     w) * 32 + 16 + kt) * 32 + lane];
            float2 bZ = g_gwP[((16 + w) * 32 + 16 + kt) * 32 + lane];
            #pragma unroll
            for (int mt = 0; mt < 3; ++mt) {
                const uint32* AH = (const uint32*)&ah[mt];
                mma8(aR1[mt], AH, bR);
                mma8(aZ1[mt], AH, bZ);
            }
        }
        // (no barrier: epi1 uses only warp-local accs; h1f access is read-read)

        // ==== layer1 epilogue 1: r,z ; write r*h1 frags (hi only) ====
        float zz1[3][4], hold1[3][4];
        #pragma unroll
        for (int mt = 0; mt < 3; ++mt)
            #pragma unroll
            for (int r = 0; r < 4; ++r) {
                int m   = mt * 16 + g + 8 * (r >> 1);
                int col = c0 + (r & 1);
                hold1[mt][r] = frag_read2(h1f, 16, mt, col >> 3, m, col);
                float rr = sigmoidf_(aR1[mt][r]);
                zz1[mt][r] = sigmoidf_(aZ1[mt][r]);
                float rh = rr * hold1[mt][r];
                frag_write(rhf, 16, 0, mt, col >> 3, m, col, tf32_rna(rh));
            }
        __syncthreads();   // S5: rhf ready; all gates-GEMM h1f reads done

        // ==== candidate r*h half ====
        #pragma unroll
        for (int kt = 0; kt < 16; ++kt) {
            uint4 ah[3];
            #pragma unroll
            for (int mt = 0; mt < 3; ++mt)
                ah[mt] = ((const uint4*)rhf)[((0 * 3 + mt) * 16 + kt) * 32 + lane];
            float2 bC = g_owP[(w * 32 + 16 + kt) * 32 + lane];
            #pragma unroll
            for (int mt = 0; mt < 3; ++mt) {
                const uint32* AH = (const uint32*)&ah[mt];
                mma8(aC[mt], AH, bC);
            }
        }

        // ==== layer1 epilogue 2: h1(t) -> h1f (hi+lo) + gmem out ====
        #pragma unroll
        for (int mt = 0; mt < 3; ++mt)
            #pragma unroll
            for (int rh = 0; rh < 2; ++rh) {
                int m = mt * 16 + g + 8 * rh;
                float hn2[2];
                #pragma unroll
                for (int c = 0; c < 2; ++c) {
                    int r = rh * 2 + c;
                    float cand = tanhf_(aC[mt][r]);
                    float hn = zz1[mt][r] * hold1[mt][r]
                             + (1.f - zz1[mt][r]) * cand;
                    float hi, lo; tf32_split(hn, hi, lo);
                    frag_write(h1f, 16, 0, mt, c0 >> 3, m, c0 + c, hi);
                    frag_write(h1f, 16, 1, mt, c0 >> 3, m, c0 + c, lo);
                    hn2[c] = hn;
                }
                int bn = bn0 + m;
                if (bn < BN)
                    *reinterpret_cast<float2*>(out + ((size_t)bn * T_ + t) * H_ + c0)
                        = make_float2(hn2[0], hn2[1]);
            }
        // no trailing barrier: next iteration's first phase only READS
    }
}

extern "C" void kernel_launch(void* const* d_in, const int* in_sizes, int n_in,
                              void* d_out, int out_size)
{
    const float* x      = (const float*)d_in[0];
    const float* w_ih   = (const float*)d_in[1];
    const float* w_hh   = (const float*)d_in[2];
    const float* b_ih   = (const float*)d_in[3];
    const float* b_hh   = (const float*)d_in[4];
    const float* gate_w = (const float*)d_in[5];
    const float* gate_b = (const float*)d_in[6];
    const float* out_w  = (const float*)d_in[7];
    const float* out_b  = (const float*)d_in[8];
    float* out = (float*)d_out;

    const int smem = (6144 + 3 * 12288) * 4;   // 172032 B
    cudaFuncSetAttribute(gru_fused, cudaFuncAttributeMaxDynamicSharedMemorySize, smem);

    prepack<<<168, 512>>>(w_ih, w_hh, gate_w, out_w);
    gru_fused<<<NCTA, NTH, smem>>>(x, b_ih, b_hh, gate_b, out_b, out);
}

// round 16
// speedup vs baseline: 1.0413x; 1.0413x over previous
#include <cuda_runtime.h>
#include <math.h>

#define BN   20800
#define T_   24
#define F_   64
#define H_   128
#define TRR  32
#define NCTA 650          // 20800 / 32 exactly
#define NTH  256          // 8 warps, 16 output cols per warp (2 n8-blocks)

typedef unsigned int uint32;

// ---------------- global scratch ----------------
// prepacked B-fragments (tf32 hi term only), float2 per (tile, lane)  [m16n8k8]
__device__ float2 g_wihP[384  * 32];   // w_ih  [384x64]  : 48 nt x 8 kt
__device__ float2 g_whhP[768  * 32];   // w_hh  [384x128] : 48 nt x 16 kt
__device__ float2 g_gwP [1024 * 32];   // gate_w[256x256] : 32 nt x 32 kt
__device__ float2 g_owP [512  * 32];   // out_w [128x256] : 16 nt x 32 kt
// packed biases: [0]=b_ih+b_hh r, [1]=..z, [2]=b_ih n, [3]=b_hh n,
//                [4]=gate_b r, [5]=gate_b z, [6]=out_b
__device__ float  g_biasP[7 * 128];

// ---------------- helpers ----------------
__device__ __forceinline__ void tf32_split(float v, float& hi, float& lo) {
    uint32 b;
    asm("cvt.rna.tf32.f32 %0, %1;" : "=r"(b) : "f"(v));
    hi = __uint_as_float(b);
    float r = v - hi;
    asm("cvt.rna.tf32.f32 %0, %1;" : "=r"(b) : "f"(r));
    lo = __uint_as_float(b);
}

__device__ __forceinline__ float tf32_rna(float v) {
    uint32 b;
    asm("cvt.rna.tf32.f32 %0, %1;" : "=r"(b) : "f"(v));
    return __uint_as_float(b);
}

__device__ __forceinline__ float sigmoidf_(float v) {
    return __fdividef(1.0f, 1.0f + __expf(-v));
}
__device__ __forceinline__ float tanhf_(float v) {
    return __fdividef(2.0f, 1.0f + __expf(-2.0f * v)) - 1.0f;
}

// D += A * B, m16n8k8 tf32 (row.col). a: 4 b32 regs, b: 2 b32 regs.
__device__ __forceinline__ void mma8(float d[4], const uint32* a, float2 b) {
    asm volatile(
        "mma.sync.aligned.m16n8k8.row.col.f32.tf32.tf32.f32 "
        "{%0,%1,%2,%3},{%4,%5,%6,%7},{%8,%9},{%0,%1,%2,%3};"
        : "+f"(d[0]), "+f"(d[1]), "+f"(d[2]), "+f"(d[3])
        : "r"(a[0]), "r"(a[1]), "r"(a[2]), "r"(a[3]),
          "r"(__float_as_uint(b.x)), "r"(__float_as_uint(b.y)));
}

// hi-only A-frag buffer (xf KT=8, rhf KT=16), MT=2: [mt][KT][lane32][reg4]
__device__ __forceinline__ void frag_write1(float* base, int KT,
                                            int mt, int kt, int m, int k, float v) {
    int lp = ((m & 7) << 2) | (k & 3);
    int rp = ((m >> 3) & 1) | (((k >> 2) & 1) << 1);
    base[((mt * KT + kt) * 32 + lp) * 4 + rp] = v;
}

// hi+lo state buffer (h0f/h1f, KT=16, MT=2): [term2][mt2][16][lane32][reg4]
__device__ __forceinline__ void frag_write2(float* base, int term,
                                            int mt, int kt, int m, int k, float v) {
    int lp = ((m & 7) << 2) | (k & 3);
    int rp = ((m >> 3) & 1) | (((k >> 2) & 1) << 1);
    base[(((term * 2 + mt) * 16 + kt) * 32 + lp) * 4 + rp] = v;
}

__device__ __forceinline__ float frag_read2(const float* base,
                                            int mt, int kt, int m, int k) {
    int lp = ((m & 7) << 2) | (k & 3);
    int rp = ((m >> 3) & 1) | (((k >> 2) & 1) << 1);
    return base[(((0 * 2 + mt) * 16 + kt) * 32 + lp) * 4 + rp]
         + base[(((1 * 2 + mt) * 16 + kt) * 32 + lp) * 4 + rp];
}

// ---------------- weight prepack into B-fragment order (hi term only) ------
__global__ void prepack(const float* __restrict__ w_ih, const float* __restrict__ w_hh,
                        const float* __restrict__ gw,  const float* __restrict__ ow)
{
    int idx = blockIdx.x * blockDim.x + threadIdx.x;   // 2688 tiles * 32 lanes
    if (idx >= 2688 * 32) return;
    int lane = idx & 31, tile = idx >> 5;
    int g = lane >> 2, tig = lane & 3;
    const float* W; float2* dst; int ld, lt;
    if      (tile < 384)  { W = w_ih; dst = g_wihP; ld = 64;  lt = tile; }
    else if (tile < 1152) { W = w_hh; dst = g_whhP; ld = 128; lt = tile - 384; }
    else if (tile < 2176) { W = gw;   dst = g_gwP;  ld = 256; lt = tile - 1152; }
    else                  { W = ow;   dst = g_owP;  ld = 256; lt = tile - 2176; }
    int KT = ld >> 3;
    int n = (lt / KT) * 8 + g;            // output row
    int k = (lt % KT) * 8 + tig;          // input col
    dst[lt * 32 + lane] = make_float2(tf32_rna(W[n * ld + k]),
                                      tf32_rna(W[n * ld + k + 4]));
}

__global__ void bias_pack(const float* __restrict__ b_ih, const float* __restrict__ b_hh,
                          const float* __restrict__ gate_b, const float* __restrict__ out_b)
{
    int i = threadIdx.x;   // 128
    g_biasP[0 * 128 + i] = b_ih[i]       + b_hh[i];
    g_biasP[1 * 128 + i] = b_ih[128 + i] + b_hh[128 + i];
    g_biasP[2 * 128 + i] = b_ih[256 + i];
    g_biasP[3 * 128 + i] = b_hh[256 + i];
    g_biasP[4 * 128 + i] = gate_b[i];
    g_biasP[5 * 128 + i] = gate_b[128 + i];
    g_biasP[6 * 128 + i] = out_b[i];
}

// ---------------- Fused 2-layer GRU over T steps ----------------
// 8 warps; warp w owns output cols [16w,16w+16) = n8 blocks {2w, 2w+1}.
// TRR=32 (mt=2), trimmed smem (90112 B) -> 2 CTAs/SM. 1-term tf32 MMAs;
// state h0/h1 kept hi+lo in smem for exact carry.
__global__ __launch_bounds__(NTH, 2)
void gru_fused(const float* __restrict__ x, float* __restrict__ out)
{
    extern __shared__ float sm[];
    float* xf  = sm;            // [2][8][32][4]      = 2048 (x tile, hi only)
    float* h0f = sm + 2048;     // [2][2][16][32][4]  = 8192 (layer0 h, hi+lo)
    float* h1f = sm + 10240;    // 8192 (layer1 h, hi+lo)
    float* rhf = sm + 18432;    // [2][16][32][4]     = 4096 (r*h1, hi only)
    const int tid = threadIdx.x;
    const int w = tid >> 5, lane = tid & 31;
    const int g = lane >> 2, tig = lane & 3;
    const int bn0 = blockIdx.x * TRR;

    // zero h0f + h1f (contiguous 16384 floats)
    for (int i = tid; i < 16384; i += NTH) h0f[i] = 0.f;

    // stage x(0): 32 rows x 64 cols, hi term only
    #pragma unroll
    for (int i = 0; i < 8; ++i) {
        int idx = tid + i * NTH;            // 0..2047
        int row = idx >> 6, col = idx & 63;
        float v = x[(size_t)(bn0 + row) * T_ * F_ + col];
        frag_write1(xf, 8, row >> 4, col >> 3, row, col, tf32_rna(v));
    }
    __syncthreads();   // init + x(0) visible

    for (int t = 0; t < T_; ++t) {
        // ==== layer0 GEMMs (1-term), 2 n-blocks per warp ====
        float aR[2][2][4], aZ[2][2][4], aNX[2][2][4], aNH[2][2][4];
        #pragma unroll
        for (int nb = 0; nb < 2; ++nb) {
            int c0n = 16 * w + 8 * nb + 2 * tig;
            float2 vr = __ldg((const float2*)(g_biasP + 0 * 128 + c0n));
            float2 vz = __ldg((const float2*)(g_biasP + 1 * 128 + c0n));
            float2 vx = __ldg((const float2*)(g_biasP + 2 * 128 + c0n));
            float2 vh = __ldg((const float2*)(g_biasP + 3 * 128 + c0n));
            #pragma unroll
            for (int mt = 0; mt < 2; ++mt) {
                aR[mt][nb][0] = vr.x; aR[mt][nb][1] = vr.y;
                aR[mt][nb][2] = vr.x; aR[mt][nb][3] = vr.y;
                aZ[mt][nb][0] = vz.x; aZ[mt][nb][1] = vz.y;
                aZ[mt][nb][2] = vz.x; aZ[mt][nb][3] = vz.y;
                aNX[mt][nb][0] = vx.x; aNX[mt][nb][1] = vx.y;
                aNX[mt][nb][2] = vx.x; aNX[mt][nb][3] = vx.y;
                aNH[mt][nb][0] = vh.x; aNH[mt][nb][1] = vh.y;
                aNH[mt][nb][2] = vh.x; aNH[mt][nb][3] = vh.y;
            }
        }
        #pragma unroll
        for (int kt = 0; kt < 8; ++kt) {        // x-part, K=64
            uint4 ah[2];
            #pragma unroll
            for (int mt = 0; mt < 2; ++mt)
                ah[mt] = ((const uint4*)xf)[((mt * 8 + kt) * 32) + lane];
            float2 bR[2], bZ[2], bN[2];
            #pragma unroll
            for (int nb = 0; nb < 2; ++nb) {
                int nt = 2 * w + nb;
                bR[nb] = g_wihP[((     nt) * 8 + kt) * 32 + lane];
                bZ[nb] = g_wihP[((16 + nt) * 8 + kt) * 32 + lane];
                bN[nb] = g_wihP[((32 + nt) * 8 + kt) * 32 + lane];
            }
            #pragma unroll
            for (int mt = 0; mt < 2; ++mt) {
                const uint32* AH = (const uint32*)&ah[mt];
                #pragma unroll
                for (int nb = 0; nb < 2; ++nb) {
                    mma8(aR[mt][nb],  AH, bR[nb]);
                    mma8(aZ[mt][nb],  AH, bZ[nb]);
                    mma8(aNX[mt][nb], AH, bN[nb]);
                }
            }
        }
        #pragma unroll
        for (int kt = 0; kt < 16; ++kt) {       // h-part, K=128 (n gate into aNH)
            uint4 ah[2];
            #pragma unroll
            for (int mt = 0; mt < 2; ++mt)
                ah[mt] = ((const uint4*)h0f)[(((0 * 2 + mt) * 16 + kt) * 32) + lane];
            float2 bR[2], bZ[2], bN[2];
            #pragma unroll
            for (int nb = 0; nb < 2; ++nb) {
                int nt = 2 * w + nb;
                bR[nb] = g_whhP[((     nt) * 16 + kt) * 32 + lane];
                bZ[nb] = g_whhP[((16 + nt) * 16 + kt) * 32 + lane];
                bN[nb] = g_whhP[((32 + nt) * 16 + kt) * 32 + lane];
            }
            #pragma unroll
            for (int mt = 0; mt < 2; ++mt) {
                const uint32* AH = (const uint32*)&ah[mt];
                #pragma unroll
                for (int nb = 0; nb < 2; ++nb) {
                    mma8(aR[mt][nb],  AH, bR[nb]);
                    mma8(aZ[mt][nb],  AH, bZ[nb]);
                    mma8(aNH[mt][nb], AH, bN[nb]);
                }
            }
        }
        __syncthreads();   // S2: all reads of h0f/xf done

        // ==== layer0 epilogue: h0(t) -> h0f (hi+lo; exact state carry) ====
        #pragma unroll
        for (int mt = 0; mt < 2; ++mt)
            #pragma unroll
            for (int nb = 0; nb < 2; ++nb)
                #pragma unroll
                for (int r = 0; r < 4; ++r) {
                    int m   = mt * 16 + g + 8 * (r >> 1);
                    int col = 16 * w + 8 * nb + 2 * tig + (r & 1);
                    float hold = frag_read2(h0f, mt, col >> 3, m, col);
                    float rr = sigmoidf_(aR[mt][nb][r]);
                    float zz = sigmoidf_(aZ[mt][nb][r]);
                    float n  = tanhf_(aNX[mt][nb][r] + rr * aNH[mt][nb][r]);
                    float hn = (1.f - zz) * n + zz * hold;
                    float hi, lo; tf32_split(hn, hi, lo);
                    frag_write2(h0f, 0, mt, col >> 3, m, col, hi);
                    frag_write2(h0f, 1, mt, col >> 3, m, col, lo);
                }
        __syncthreads();   // S3: h0f(t) ready for layer1

        // ==== stage x(t+1) into xf (overlaps with gates GEMM below) ====
        if (t + 1 < T_) {
            #pragma unroll
            for (int i = 0; i < 8; ++i) {
                int idx = tid + i * NTH;        // 0..2047
                int row = idx >> 6, col = idx & 63;
                float v = x[((size_t)(bn0 + row) * T_ + t + 1) * F_ + col];
                frag_write1(xf, 8, row >> 4, col >> 3, row, col, tf32_rna(v));
            }
        }

        // ==== layer1 gates GEMM (+ candidate x-half) ====
        float aR1[2][2][4], aZ1[2][2][4], aC[2][2][4];
        #pragma unroll
        for (int nb = 0; nb < 2; ++nb) {
            int c0n = 16 * w + 8 * nb + 2 * tig;
            float2 vr = __ldg((const float2*)(g_biasP + 4 * 128 + c0n));
            float2 vz = __ldg((const float2*)(g_biasP + 5 * 128 + c0n));
            float2 vo = __ldg((const float2*)(g_biasP + 6 * 128 + c0n));
            #pragma unroll
            for (int mt = 0; mt < 2; ++mt) {
                aR1[mt][nb][0] = vr.x; aR1[mt][nb][1] = vr.y;
                aR1[mt][nb][2] = vr.x; aR1[mt][nb][3] = vr.y;
                aZ1[mt][nb][0] = vz.x; aZ1[mt][nb][1] = vz.y;
                aZ1[mt][nb][2] = vz.x; aZ1[mt][nb][3] = vz.y;
                aC[mt][nb][0]  = vo.x; aC[mt][nb][1]  = vo.y;
                aC[mt][nb][2]  = vo.x; aC[mt][nb][3]  = vo.y;
            }
        }
        #pragma unroll
        for (int kt = 0; kt < 16; ++kt) {       // x half: A = h0f (hi)
            uint4 ah[2];
            #pragma unroll
            for (int mt = 0; mt < 2; ++mt)
                ah[mt] = ((const uint4*)h0f)[(((0 * 2 + mt) * 16 + kt) * 32) + lane];
            float2 bR[2], bZ[2], bC[2];
            #pragma unroll
            for (int nb = 0; nb < 2; ++nb) {
                int nt = 2 * w + nb;
                bR[nb] = g_gwP[((     nt) * 32 + kt) * 32 + lane];
                bZ[nb] = g_gwP[((16 + nt) * 32 + kt) * 32 + lane];
                bC[nb] = g_owP[(      nt  * 32 + kt) * 32 + lane];
            }
            #pragma unroll
            for (int mt = 0; mt < 2; ++mt) {
                const uint32* AH = (const uint32*)&ah[mt];
                #pragma unroll
                for (int nb = 0; nb < 2; ++nb) {
                    mma8(aR1[mt][nb], AH, bR[nb]);
                    mma8(aZ1[mt][nb], AH, bZ[nb]);
                    mma8(aC[mt][nb],  AH, bC[nb]);
                }
            }
        }
        #pragma unroll
        for (int kt = 0; kt < 16; ++kt) {       // h half: A = h1f (hi), gates only
            uint4 ah[2];
            #pragma unroll
            for (int mt = 0; mt < 2; ++mt)
                ah[mt] = ((const uint4*)h1f)[(((0 * 2 + mt) * 16 + kt) * 32) + lane];
            float2 bR[2], bZ[2];
            #pragma unroll
            for (int nb = 0; nb < 2; ++nb) {
                int nt = 2 * w + nb;
                bR[nb] = g_gwP[((     nt) * 32 + 16 + kt) * 32 + lane];
                bZ[nb] = g_gwP[((16 + nt) * 32 + 16 + kt) * 32 + lane];
            }
            #pragma unroll
            for (int mt = 0; mt < 2; ++mt) {
                const uint32* AH = (const uint32*)&ah[mt];
                #pragma unroll
                for (int nb = 0; nb < 2; ++nb) {
                    mma8(aR1[mt][nb], AH, bR[nb]);
                    mma8(aZ1[mt][nb], AH, bZ[nb]);
                }
            }
        }
        // (no barrier: epi1 uses only warp-local accs; h1f access is read-read)

        // ==== layer1 epilogue 1: r ; write r*h1 frags (hi only; z deferred) ====
        #pragma unroll
        for (int mt = 0; mt < 2; ++mt)
            #pragma unroll
            for (int nb = 0; nb < 2; ++nb)
                #pragma unroll
                for (int r = 0; r < 4; ++r) {
                    int m   = mt * 16 + g + 8 * (r >> 1);
                    int col = 16 * w + 8 * nb + 2 * tig + (r & 1);
                    float hold = frag_read2(h1f, mt, col >> 3, m, col);
                    float rr = sigmoidf_(aR1[mt][nb][r]);
                    float rh = rr * hold;
                    frag_write1(rhf, 16, mt, col >> 3, m, col, tf32_rna(rh));
                }
        __syncthreads();   // S5: rhf ready; all gates-GEMM h1f reads done

        // ==== candidate r*h half ====
        #pragma unroll
        for (int kt = 0; kt < 16; ++kt) {
            uint4 ah[2];
            #pragma unroll
            for (int mt = 0; mt < 2; ++mt)
                ah[mt] = ((const uint4*)rhf)[((mt * 16 + kt) * 32) + lane];
            float2 bC[2];
            #pragma unroll
            for (int nb = 0; nb < 2; ++nb)
                bC[nb] = g_owP[((2 * w + nb) * 32 + 16 + kt) * 32 + lane];
            #pragma unroll
            for (int mt = 0; mt < 2; ++mt) {
                const uint32* AH = (const uint32*)&ah[mt];
                #pragma unroll
                for (int nb = 0; nb < 2; ++nb)
                    mma8(aC[mt][nb], AH, bC[nb]);
            }
        }

        // ==== layer1 epilogue 2: z + h update -> h1f (hi+lo) + gmem out ====
        // hold re-read from h1f (unchanged since epi1); z recomputed from aZ1.
        #pragma unroll
        for (int mt = 0; mt < 2; ++mt)
            #pragma unroll
            for (int nb = 0; nb < 2; ++nb)
                #pragma unroll
                for (int rh = 0; rh < 2; ++rh) {
                    int m  = mt * 16 + g + 8 * rh;
                    int c0 = 16 * w + 8 * nb + 2 * tig;
                    float hn2[2];
                    #pragma unroll
                    for (int c = 0; c < 2; ++c) {
                        int r = rh * 2 + c;
                        float hold = frag_read2(h1f, mt, c0 >> 3, m, c0 + c);
                        float zz = sigmoidf_(aZ1[mt][nb][r]);
                        float cand = tanhf_(aC[mt][nb][r]);
                        float hn = zz * hold + (1.f - zz) * cand;
                        float hi, lo; tf32_split(hn, hi, lo);
                        frag_write2(h1f, 0, mt, c0 >> 3, m, c0 + c, hi);
                        frag_write2(h1f, 1, mt, c0 >> 3, m, c0 + c, lo);
                        hn2[c] = hn;
                    }
                    *reinterpret_cast<float2*>(out + ((size_t)(bn0 + m) * T_ + t) * H_ + c0)
                        = make_float2(hn2[0], hn2[1]);
                }
        // no trailing barrier: next iteration's first phase only READS
    }
}

extern "C" void kernel_launch(void* const* d_in, const int* in_sizes, int n_in,
                              void* d_out, int out_size)
{
    const float* x      = (const float*)d_in[0];
    const float* w_ih   = (const float*)d_in[1];
    const float* w_hh   = (const float*)d_in[2];
    const float* b_ih   = (const float*)d_in[3];
    const float* b_hh   = (const float*)d_in[4];
    const float* gate_w = (const float*)d_in[5];
    const float* gate_b = (const float*)d_in[6];
    const float* out_w  = (const float*)d_in[7];
    const float* out_b  = (const float*)d_in[8];
    float* out = (float*)d_out;

    const int smem = 22528 * 4;   // 90112 B -> 2 CTAs/SM (180224 B total)
    cudaFuncSetAttribute(gru_fused, cudaFuncAttributeMaxDynamicSharedMemorySize, smem);

    prepack<<<168, 512>>>(w_ih, w_hh, gate_w, out_w);
    bias_pack<<<1, 128>>>(b_ih, b_hh, gate_b, out_b);
    gru_fused<<<NCTA, NTH, smem>>>(x, out);
}

// round 17
// speedup vs baseline: 1.8793x; 1.8048x over previous
#include <cuda_runtime.h>
#include <cuda_fp16.h>
#include <math.h>

#define BN   20800
#define T_   24
#define F_   64
#define H_   128
#define TRR  48
#define NCTA 434          // ceil(20800/48)
#define NTH  256          // 8 warps, 16 output cols per warp (2 n8-blocks)

typedef unsigned int uint32;

// ---------------- global scratch ----------------
// prepacked fp16 B-fragments for m16n8k16: uint2 per (tile, lane)
// tile = 8 n-rows x 16 k-cols; lane: .x = half2(W[n][k0],W[n][k0+1]),
//                                    .y = half2(W[n][k0+8],W[n][k0+9])
__device__ uint2 g_wihP[192 * 32];   // w_ih  [384x64]  : 48 nt x 4 kt
__device__ uint2 g_whhP[384 * 32];   // w_hh  [384x128] : 48 nt x 8 kt
__device__ uint2 g_gwP [512 * 32];   // gate_w[256x256] : 32 nt x 16 kt
__device__ uint2 g_owP [256 * 32];   // out_w [128x256] : 16 nt x 16 kt
// packed biases: [0]=b_ih+b_hh r, [1]=..z, [2]=b_ih n, [3]=b_hh n,
//                [4]=gate_b r, [5]=gate_b z, [6]=out_b
__device__ float g_biasP[7 * 128];

// ---------------- helpers ----------------
__device__ __forceinline__ uint32 pack_h2(float a, float b) {
    __half2 h = __floats2half2_rn(a, b);
    return *reinterpret_cast<uint32*>(&h);
}

__device__ __forceinline__ float sigmoidf_(float v) {
    return __fdividef(1.0f, 1.0f + __expf(-v));
}
__device__ __forceinline__ float tanhf_(float v) {
    return __fdividef(2.0f, 1.0f + __expf(-2.0f * v)) - 1.0f;
}

// D += A * B, m16n8k16 fp16 inputs, fp32 accum (row.col)
__device__ __forceinline__ void mma16(float d[4], const uint32* a, uint2 b) {
    asm volatile(
        "mma.sync.aligned.m16n8k16.row.col.f32.f16.f16.f32 "
        "{%0,%1,%2,%3},{%4,%5,%6,%7},{%8,%9},{%0,%1,%2,%3};"
        : "+f"(d[0]), "+f"(d[1]), "+f"(d[2]), "+f"(d[3])
        : "r"(a[0]), "r"(a[1]), "r"(a[2]), "r"(a[3]),
          "r"(b.x), "r"(b.y));
}

// fp16 A-frag smem: [mt(3)][kt(KT)][lane(32)][reg(4)] u32.
// Writes half2 covering (m, col..col+1), col even.
__device__ __forceinline__ void fwrh(uint32* base, int KT,
                                     int mt, int m, int col, uint32 v) {
    int kt = col >> 4, kk = col & 15;
    int lp = ((m & 7) << 2) | ((kk >> 1) & 3);
    int rp = ((m >> 3) & 1) | (((kk >> 3) & 1) << 1);
    base[((mt * KT + kt) * 32 + lp) * 4 + rp] = v;
}

// exact f32 state: [mt(3)][kt16][lane(32)][reg(4)] floats (k8-granular map)
__device__ __forceinline__ void fwrs(float* base, int mt, int m, int k, float v) {
    int kt = k >> 3, kk = k & 7;
    int lp = ((m & 7) << 2) | (kk & 3);
    int rp = ((m >> 3) & 1) | (((kk >> 2) & 1) << 1);
    base[((mt * 16 + kt) * 32 + lp) * 4 + rp] = v;
}
__device__ __forceinline__ float frds(const float* base, int mt, int m, int k) {
    int kt = k >> 3, kk = k & 7;
    int lp = ((m & 7) << 2) | (kk & 3);
    int rp = ((m >> 3) & 1) | (((kk >> 2) & 1) << 1);
    return base[((mt * 16 + kt) * 32 + lp) * 4 + rp];
}

// ---------------- weight prepack into fp16 B-fragment order ----------------
// 1344 tiles total: wih 192, whh 384, gw 512, ow 256.
__global__ void prepack(const float* __restrict__ w_ih, const float* __restrict__ w_hh,
                        const float* __restrict__ gw,  const float* __restrict__ ow)
{
    int idx = blockIdx.x * blockDim.x + threadIdx.x;
    if (idx >= 1344 * 32) return;
    int lane = idx & 31, tile = idx >> 5;
    int g = lane >> 2, tig = lane & 3;
    const float* W; uint2* dst; int ld, lt;
    if      (tile < 192)  { W = w_ih; dst = g_wihP; ld = 64;  lt = tile; }
    else if (tile < 576)  { W = w_hh; dst = g_whhP; ld = 128; lt = tile - 192; }
    else if (tile < 1088) { W = gw;   dst = g_gwP;  ld = 256; lt = tile - 576; }
    else                  { W = ow;   dst = g_owP;  ld = 256; lt = tile - 1088; }
    int KT = ld >> 4;
    int n = (lt / KT) * 8 + g;
    int k = (lt % KT) * 16 + tig * 2;
    dst[lt * 32 + lane] = make_uint2(pack_h2(W[n * ld + k],     W[n * ld + k + 1]),
                                     pack_h2(W[n * ld + k + 8], W[n * ld + k + 9]));
}

__global__ void bias_pack(const float* __restrict__ b_ih, const float* __restrict__ b_hh,
                          const float* __restrict__ gate_b, const float* __restrict__ out_b)
{
    int i = threadIdx.x;   // 128
    g_biasP[0 * 128 + i] = b_ih[i]       + b_hh[i];
    g_biasP[1 * 128 + i] = b_ih[128 + i] + b_hh[128 + i];
    g_biasP[2 * 128 + i] = b_ih[256 + i];
    g_biasP[3 * 128 + i] = b_hh[256 + i];
    g_biasP[4 * 128 + i] = gate_b[i];
    g_biasP[5 * 128 + i] = gate_b[128 + i];
    g_biasP[6 * 128 + i] = out_b[i];
}

// ---------------- Fused 2-layer GRU over T steps ----------------
// 8 warps; warp w owns output cols [16w,16w+16) = n8 blocks {2w, 2w+1}.
// fp16 m16n8k16 MMAs; recurrent state carried exact-f32 in h0s/h1s.
__global__ __launch_bounds__(NTH, 1)
void gru_fused(const float* __restrict__ x, float* __restrict__ out)
{
    extern __shared__ float sm[];
    uint32* xf  = (uint32*)sm;          // [3][4][32][4]  = 1536 u32 (x fp16)
    uint32* h0m = (uint32*)sm + 1536;   // [3][8][32][4]  = 3072 (h0 fp16)
    uint32* h1m = (uint32*)sm + 4608;   // 3072 (h1 fp16)
    uint32* rhm = (uint32*)sm + 7680;   // 3072 (r*h1 fp16)
    float*  h0s = sm + 10752;           // [3][16][32][4] = 6144 f32 (h0 exact)
    float*  h1s = sm + 16896;           // 6144 f32 (h1 exact)
    const int tid = threadIdx.x;
    const int w = tid >> 5, lane = tid & 31;
    const int g = lane >> 2, tig = lane & 3;
    const int bn0 = blockIdx.x * TRR;

    // zero fp16 h frags (h0m,h1m contiguous) and exact states
    for (int i = tid; i < 6144; i += NTH) h0m[i] = 0u;
    for (int i = tid; i < 12288; i += NTH) h0s[i] = 0.f;

    // stage x(0): 48 rows x 64 cols as fp16 pairs
    #pragma unroll
    for (int i = 0; i < 6; ++i) {
        int idx = tid + i * NTH;            // 0..1535 col-pairs
        int row = idx >> 5, col = (idx & 31) * 2;
        int bn = bn0 + row;
        float2 v = make_float2(0.f, 0.f);
        if (bn < BN)
            v = *reinterpret_cast<const float2*>(x + (size_t)bn * T_ * F_ + col);
        fwrh(xf, 4, row >> 4, row, col, pack_h2(v.x, v.y));
    }
    __syncthreads();   // init + x(0) visible

    for (int t = 0; t < T_; ++t) {
        // ==== layer0 GEMMs, 2 n-blocks per warp ====
        float aR[3][2][4], aZ[3][2][4], aNX[3][2][4], aNH[3][2][4];
        #pragma unroll
        for (int nb = 0; nb < 2; ++nb) {
            int c0n = 16 * w + 8 * nb + 2 * tig;
            float2 vr = __ldg((const float2*)(g_biasP + 0 * 128 + c0n));
            float2 vz = __ldg((const float2*)(g_biasP + 1 * 128 + c0n));
            float2 vx = __ldg((const float2*)(g_biasP + 2 * 128 + c0n));
            float2 vh = __ldg((const float2*)(g_biasP + 3 * 128 + c0n));
            #pragma unroll
            for (int mt = 0; mt < 3; ++mt) {
                aR[mt][nb][0] = vr.x; aR[mt][nb][1] = vr.y;
                aR[mt][nb][2] = vr.x; aR[mt][nb][3] = vr.y;
                aZ[mt][nb][0] = vz.x; aZ[mt][nb][1] = vz.y;
                aZ[mt][nb][2] = vz.x; aZ[mt][nb][3] = vz.y;
                aNX[mt][nb][0] = vx.x; aNX[mt][nb][1] = vx.y;
                aNX[mt][nb][2] = vx.x; aNX[mt][nb][3] = vx.y;
                aNH[mt][nb][0] = vh.x; aNH[mt][nb][1] = vh.y;
                aNH[mt][nb][2] = vh.x; aNH[mt][nb][3] = vh.y;
            }
        }
        #pragma unroll
        for (int kt = 0; kt < 4; ++kt) {        // x-part, K=64
            uint4 ah[3];
            #pragma unroll
            for (int mt = 0; mt < 3; ++mt)
                ah[mt] = ((const uint4*)xf)[(mt * 4 + kt) * 32 + lane];
            uint2 bR[2], bZ[2], bN[2];
            #pragma unroll
            for (int nb = 0; nb < 2; ++nb) {
                int nt = 2 * w + nb;
                bR[nb] = g_wihP[((     nt) * 4 + kt) * 32 + lane];
                bZ[nb] = g_wihP[((16 + nt) * 4 + kt) * 32 + lane];
                bN[nb] = g_wihP[((32 + nt) * 4 + kt) * 32 + lane];
            }
            #pragma unroll
            for (int mt = 0; mt < 3; ++mt) {
                const uint32* AH = (const uint32*)&ah[mt];
                #pragma unroll
                for (int nb = 0; nb < 2; ++nb) {
                    mma16(aR[mt][nb],  AH, bR[nb]);
                    mma16(aZ[mt][nb],  AH, bZ[nb]);
                    mma16(aNX[mt][nb], AH, bN[nb]);
                }
            }
        }
        #pragma unroll
        for (int kt = 0; kt < 8; ++kt) {        // h-part, K=128 (n gate into aNH)
            uint4 ah[3];
            #pragma unroll
            for (int mt = 0; mt < 3; ++mt)
                ah[mt] = ((const uint4*)h0m)[(mt * 8 + kt) * 32 + lane];
            uint2 bR[2], bZ[2], bN[2];
            #pragma unroll
            for (int nb = 0; nb < 2; ++nb) {
                int nt = 2 * w + nb;
                bR[nb] = g_whhP[((     nt) * 8 + kt) * 32 + lane];
                bZ[nb] = g_whhP[((16 + nt) * 8 + kt) * 32 + lane];
                bN[nb] = g_whhP[((32 + nt) * 8 + kt) * 32 + lane];
            }
            #pragma unroll
            for (int mt = 0; mt < 3; ++mt) {
                const uint32* AH = (const uint32*)&ah[mt];
                #pragma unroll
                for (int nb = 0; nb < 2; ++nb) {
                    mma16(aR[mt][nb],  AH, bR[nb]);
                    mma16(aZ[mt][nb],  AH, bZ[nb]);
                    mma16(aNH[mt][nb], AH, bN[nb]);
                }
            }
        }
        __syncthreads();   // S2: all reads of h0m/xf done

        // ==== layer0 epilogue: h0(t) -> h0s (exact) + h0m (fp16) ====
        #pragma unroll
        for (int mt = 0; mt < 3; ++mt)
            #pragma unroll
            for (int nb = 0; nb < 2; ++nb)
                #pragma unroll
                for (int rh = 0; rh < 2; ++rh) {
                    int m   = mt * 16 + g + 8 * rh;
                    int c0b = 16 * w + 8 * nb + 2 * tig;
                    float hn2[2];
                    #pragma unroll
                    for (int c = 0; c < 2; ++c) {
                        int r = rh * 2 + c;
                        int col = c0b + c;
                        float hold = frds(h0s, mt, m, col);
                        float rr = sigmoidf_(aR[mt][nb][r]);
                        float zz = sigmoidf_(aZ[mt][nb][r]);
                        float n  = tanhf_(aNX[mt][nb][r] + rr * aNH[mt][nb][r]);
                        float hn = (1.f - zz) * n + zz * hold;
                        fwrs(h0s, mt, m, col, hn);
                        hn2[c] = hn;
                    }
                    fwrh(h0m, 8, mt, m, c0b, pack_h2(hn2[0], hn2[1]));
                }
        __syncthreads();   // S3: h0(t) ready for layer1

        // ==== stage x(t+1) into xf (overlaps with gates GEMM below) ====
        if (t + 1 < T_) {
            #pragma unroll
            for (int i = 0; i < 6; ++i) {
                int idx = tid + i * NTH;        // 0..1535 col-pairs
                int row = idx >> 5, col = (idx & 31) * 2;
                int bn = bn0 + row;
                float2 v = make_float2(0.f, 0.f);
                if (bn < BN)
                    v = *reinterpret_cast<const float2*>(
                            x + ((size_t)bn * T_ + t + 1) * F_ + col);
                fwrh(xf, 4, row >> 4, row, col, pack_h2(v.x, v.y));
            }
        }

        // ==== layer1 gates GEMM (+ candidate x-half) ====
        float aR1[3][2][4], aZ1[3][2][4], aC[3][2][4];
        #pragma unroll
        for (int nb = 0; nb < 2; ++nb) {
            int c0n = 16 * w + 8 * nb + 2 * tig;
            float2 vr = __ldg((const float2*)(g_biasP + 4 * 128 + c0n));
            float2 vz = __ldg((const float2*)(g_biasP + 5 * 128 + c0n));
            float2 vo = __ldg((const float2*)(g_biasP + 6 * 128 + c0n));
            #pragma unroll
            for (int mt = 0; mt < 3; ++mt) {
                aR1[mt][nb][0] = vr.x; aR1[mt][nb][1] = vr.y;
                aR1[mt][nb][2] = vr.x; aR1[mt][nb][3] = vr.y;
                aZ1[mt][nb][0] = vz.x; aZ1[mt][nb][1] = vz.y;
                aZ1[mt][nb][2] = vz.x; aZ1[mt][nb][3] = vz.y;
                aC[mt][nb][0]  = vo.x; aC[mt][nb][1]  = vo.y;
                aC[mt][nb][2]  = vo.x; aC[mt][nb][3]  = vo.y;
            }
        }
        #pragma unroll
        for (int kt = 0; kt < 8; ++kt) {        // x half: A = h0m
            uint4 ah[3];
            #pragma unroll
            for (int mt = 0; mt < 3; ++mt)
                ah[mt] = ((const uint4*)h0m)[(mt * 8 + kt) * 32 + lane];
            uint2 bR[2], bZ[2], bC[2];
            #pragma unroll
            for (int nb = 0; nb < 2; ++nb) {
                int nt = 2 * w + nb;
                bR[nb] = g_gwP[((     nt) * 16 + kt) * 32 + lane];
                bZ[nb] = g_gwP[((16 + nt) * 16 + kt) * 32 + lane];
                bC[nb] = g_owP[(      nt  * 16 + kt) * 32 + lane];
            }
            #pragma unroll
            for (int mt = 0; mt < 3; ++mt) {
                const uint32* AH = (const uint32*)&ah[mt];
                #pragma unroll
                for (int nb = 0; nb < 2; ++nb) {
                    mma16(aR1[mt][nb], AH, bR[nb]);
                    mma16(aZ1[mt][nb], AH, bZ[nb]);
                    mma16(aC[mt][nb],  AH, bC[nb]);
                }
            }
        }
        #pragma unroll
        for (int kt = 0; kt < 8; ++kt) {        // h half: A = h1m, gates only
            uint4 ah[3];
            #pragma unroll
            for (int mt = 0; mt < 3; ++mt)
                ah[mt] = ((const uint4*)h1m)[(mt * 8 + kt) * 32 + lane];
            uint2 bR[2], bZ[2];
            #pragma unroll
            for (int nb = 0; nb < 2; ++nb) {
                int nt = 2 * w + nb;
                bR[nb] = g_gwP[((     nt) * 16 + 8 + kt) * 32 + lane];
                bZ[nb] = g_gwP[((16 + nt) * 16 + 8 + kt) * 32 + lane];
            }
            #pragma unroll
            for (int mt = 0; mt < 3; ++mt) {
                const uint32* AH = (const uint32*)&ah[mt];
                #pragma unroll
                for (int nb = 0; nb < 2; ++nb) {
                    mma16(aR1[mt][nb], AH, bR[nb]);
                    mma16(aZ1[mt][nb], AH, bZ[nb]);
                }
            }
        }
        // (no barrier: epi1 uses only warp-local accs; h1s/h1m reads are
        //  self-written / read-read; rhm old readers done before S5(t-1)+S2/S3)

        // ==== layer1 epilogue 1: r,z ; write r*h1 fp16 frags ====
        float zz1[3][2][4], hold1[3][2][4];
        #pragma unroll
        for (int mt = 0; mt < 3; ++mt)
            #pragma unroll
            for (int nb = 0; nb < 2; ++nb)
                #pragma unroll
                for (int rh = 0; rh < 2; ++rh) {
                    int m   = mt * 16 + g + 8 * rh;
                    int c0b = 16 * w + 8 * nb + 2 * tig;
                    float rh2[2];
                    #pragma unroll
                    for (int c = 0; c < 2; ++c) {
                        int r = rh * 2 + c;
                        hold1[mt][nb][r] = frds(h1s, mt, m, c0b + c);
                        float rr = sigmoidf_(aR1[mt][nb][r]);
                        zz1[mt][nb][r] = sigmoidf_(aZ1[mt][nb][r]);
                        rh2[c] = rr * hold1[mt][nb][r];
                    }
                    fwrh(rhm, 8, mt, m, c0b, pack_h2(rh2[0], rh2[1]));
                }
        __syncthreads();   // S5: rhm ready; all gates-GEMM h1m reads done

        // ==== candidate r*h half ====
        #pragma unroll
        for (int kt = 0; kt < 8; ++kt) {
            uint4 ah[3];
            #pragma unroll
            for (int mt = 0; mt < 3; ++mt)
                ah[mt] = ((const uint4*)rhm)[(mt * 8 + kt) * 32 + lane];
            uint2 bC[2];
            #pragma unroll
            for (int nb = 0; nb < 2; ++nb)
                bC[nb] = g_owP[((2 * w + nb) * 16 + 8 + kt) * 32 + lane];
            #pragma unroll
            for (int mt = 0; mt < 3; ++mt) {
                const uint32* AH = (const uint32*)&ah[mt];
                #pragma unroll
                for (int nb = 0; nb < 2; ++nb)
                    mma16(aC[mt][nb], AH, bC[nb]);
            }
        }

        // ==== layer1 epilogue 2: h1(t) -> h1s + h1m + gmem out ====
        #pragma unroll
        for (int mt = 0; mt < 3; ++mt)
            #pragma unroll
            for (int nb = 0; nb < 2; ++nb)
                #pragma unroll
                for (int rh = 0; rh < 2; ++rh) {
                    int m   = mt * 16 + g + 8 * rh;
                    int c0b = 16 * w + 8 * nb + 2 * tig;
                    float hn2[2];
                    #pragma unroll
                    for (int c = 0; c < 2; ++c) {
                        int r = rh * 2 + c;
                        float cand = tanhf_(aC[mt][nb][r]);
                        float hn = zz1[mt][nb][r] * hold1[mt][nb][r]
                                 + (1.f - zz1[mt][nb][r]) * cand;
                        fwrs(h1s, mt, m, c0b + c, hn);
                        hn2[c] = hn;
                    }
                    fwrh(h1m, 8, mt, m, c0b, pack_h2(hn2[0], hn2[1]));
                    int bn = bn0 + m;
                    if (bn < BN)
                        *reinterpret_cast<float2*>(out + ((size_t)bn * T_ + t) * H_ + c0b)
                            = make_float2(hn2[0], hn2[1]);
                }
        // no trailing barrier: next iteration's first phase only READS,
        // and all its inputs were barrier-ordered (S3/S5 of this step).
    }
}

extern "C" void kernel_launch(void* const* d_in, const int* in_sizes, int n_in,
                              void* d_out, int out_size)
{
    const float* x      = (const float*)d_in[0];
    const float* w_ih   = (const float*)d_in[1];
    const float* w_hh   = (const float*)d_in[2];
    const float* b_ih   = (const float*)d_in[3];
    const float* b_hh   = (const float*)d_in[4];
    const float* gate_w = (const float*)d_in[5];
    const float* gate_b = (const float*)d_in[6];
    const float* out_w  = (const float*)d_in[7];
    const float* out_b  = (const float*)d_in[8];
    float* out = (float*)d_out;

    const int smem = 23040 * 4;   // 92160 B
    cudaFuncSetAttribute(gru_fused, cudaFuncAttributeMaxDynamicSharedMemorySize, smem);

    prepack<<<84, 512>>>(w_ih, w_hh, gate_w, out_w);   // 84*512 = 43008 = 1344*32
    bias_pack<<<1, 128>>>(b_ih, b_hh, gate_b, out_b);
    gru_fused<<<NCTA, NTH, smem>>>(x, out);
}